// round 8
// baseline (speedup 1.0000x reference)
#include <cuda_runtime.h>
#include <cuda_bf16.h>

// MatrixFactorization: out[r] = dot(concat(Wd[dow],Wt[time],Wm[month],Wdy[day]), W_item[dest])
// N=1048576, NUM_FACTOR=128, NUM_DIM=32.
//
// R8 = R3 (warp-per-row loads, 16-load front-batch per 8-row batch, merged
// 16-shuffle reduction, vectorized index loads) with ROWS_PER_WARP=32:
// 4 independent unrolled batches per warp so batch b+1's loads overlap batch
// b's reduce/store epilogue. 32-bit item offsets (di*128 < 2^31).

#define WARPS_PER_BLOCK 8
#define THREADS (WARPS_PER_BLOCK * 32)
#define BATCH 8
#define ROWS_PER_WARP 32   // 4 batches of 8

__global__ __launch_bounds__(THREADS)
void mf_kernel(const int* __restrict__ dow,
               const int* __restrict__ tim,
               const int* __restrict__ mon,
               const int* __restrict__ day,
               const int* __restrict__ dest,
               const float* __restrict__ Wdow,
               const float* __restrict__ Wtim,
               const float* __restrict__ Wmon,
               const float* __restrict__ Wday,
               const float* __restrict__ Witem,
               float* __restrict__ out,
               int n)
{
    const int warp_id = blockIdx.x * WARPS_PER_BLOCK + (threadIdx.x >> 5);
    const int lane = threadIdx.x & 31;
    const int sub = lane >> 3;        // which small table (0..3)
    const int off = (lane & 7) * 4;   // float offset within 32-dim embedding

    const float* __restrict__ Wsub =
        (sub == 0) ? Wdow : (sub == 1) ? Wtim : (sub == 2) ? Wmon : Wday;
    const int* __restrict__ idx_arr =
        (sub == 0) ? dow : (sub == 1) ? tim : (sub == 2) ? mon : day;

    // Lane that ends up holding row i of the batch after the merged tree:
    //   bit4(lane)=i bit0, bit3(lane)=i bit1, bit2(lane)=i bit2, bits0-1=0.
    const int rowid = ((lane >> 4) & 1) | (((lane >> 3) & 1) << 1) | (((lane >> 2) & 1) << 2);
    const bool is_writer = ((lane & 3) == 0);

    const int base = warp_id * ROWS_PER_WARP;
    if (base >= n) return;

#pragma unroll
    for (int b = 0; b < ROWS_PER_WARP / BATCH; b++) {
        const int rb = base + b * BATCH;

        // ---- Vectorized index loads: rb is 8-aligned -> 32B-aligned int4 ----
        int si_v[BATCH];
        int di_v[BATCH];
        {
            const int4 ia = *reinterpret_cast<const int4*>(idx_arr + rb);
            const int4 ib = *reinterpret_cast<const int4*>(idx_arr + rb + 4);
            const int4 da = *reinterpret_cast<const int4*>(dest + rb);
            const int4 db = *reinterpret_cast<const int4*>(dest + rb + 4);
            si_v[0] = ia.x; si_v[1] = ia.y; si_v[2] = ia.z; si_v[3] = ia.w;
            si_v[4] = ib.x; si_v[5] = ib.y; si_v[6] = ib.z; si_v[7] = ib.w;
            di_v[0] = da.x; di_v[1] = da.y; di_v[2] = da.z; di_v[3] = da.w;
            di_v[4] = db.x; di_v[5] = db.y; di_v[6] = db.z; di_v[7] = db.w;
        }

        // ---- All 16 data loads front-batched (max MLP on the L2 path) ----
        float s[BATCH];
#pragma unroll
        for (int i = 0; i < BATCH; i++) {
            const float4 u = *reinterpret_cast<const float4*>(Wsub + (si_v[i] * 32 + off));
            const float4 v = *reinterpret_cast<const float4*>(Witem + (di_v[i] * 128 + lane * 4));
            float acc = u.x * v.x;
            acc = fmaf(u.y, v.y, acc);
            acc = fmaf(u.z, v.z, acc);
            acc = fmaf(u.w, v.w, acc);
            s[i] = acc;
        }

        // ---- Merged reduction: 16 shuffles for 8 rows ----
#pragma unroll
        for (int i = 0; i < BATCH; i++)
            s[i] += __shfl_xor_sync(0xFFFFFFFFu, s[i], 16);
        float t[4];
#pragma unroll
        for (int i = 0; i < 4; i++)
            t[i] = (lane < 16) ? s[2 * i] : s[2 * i + 1];
#pragma unroll
        for (int i = 0; i < 4; i++)
            t[i] += __shfl_xor_sync(0xFFFFFFFFu, t[i], 8);
        float q[2];
#pragma unroll
        for (int i = 0; i < 2; i++)
            q[i] = ((lane & 8) == 0) ? t[2 * i] : t[2 * i + 1];
#pragma unroll
        for (int i = 0; i < 2; i++)
            q[i] += __shfl_xor_sync(0xFFFFFFFFu, q[i], 4);
        float z = ((lane & 4) == 0) ? q[0] : q[1];
        z += __shfl_xor_sync(0xFFFFFFFFu, z, 2);
        z += __shfl_xor_sync(0xFFFFFFFFu, z, 1);

        // 8 writer lanes, contiguous out[rb..rb+7] -> one 32B sector.
        if (is_writer) out[rb + rowid] = z;
    }
}

extern "C" void kernel_launch(void* const* d_in, const int* in_sizes, int n_in,
                              void* d_out, int out_size)
{
    const int*   dow   = (const int*)d_in[0];
    const int*   tim   = (const int*)d_in[1];
    const int*   mon   = (const int*)d_in[2];
    const int*   day   = (const int*)d_in[3];
    const int*   dest  = (const int*)d_in[4];
    const float* Wdow  = (const float*)d_in[5];
    const float* Wtim  = (const float*)d_in[6];
    const float* Wmon  = (const float*)d_in[7];
    const float* Wday  = (const float*)d_in[8];
    const float* Witem = (const float*)d_in[9];
    float* out = (float*)d_out;

    const int n = in_sizes[0];
    const int rows_per_block = WARPS_PER_BLOCK * ROWS_PER_WARP;  // 256
    const int grid = (n + rows_per_block - 1) / rows_per_block;

    mf_kernel<<<grid, THREADS>>>(dow, tim, mon, day, dest,
                                 Wdow, Wtim, Wmon, Wday, Witem, out, n);
}

// round 9
// speedup vs baseline: 1.4249x; 1.4249x over previous
#include <cuda_runtime.h>
#include <cuda_bf16.h>

// MatrixFactorization: out[r] = dot(concat(Wd[dow],Wt[time],Wm[month],Wdy[day]), W_item[dest])
// N=1048576, NUM_FACTOR=128, NUM_DIM=32.
//
// R9 = R3 body (warp-per-row loads, 16-load front-batch per 8-row batch,
// merged 16-shuffle reduction, vectorized index loads, 2 batches/warp = no
// spill at regs~53) with finer launch geometry: 128-thread blocks,
// __launch_bounds__(128, 9) -> reg cap 56 (no spill), 9 blocks/SM = 36 warps
// resident (vs 32 at 256-thread blocks).

#define WARPS_PER_BLOCK 4
#define THREADS (WARPS_PER_BLOCK * 32)
#define BATCH 8
#define ROWS_PER_WARP 16   // 2 batches of 8 (empirically optimal: R3 vs R6/R8)

__global__ __launch_bounds__(THREADS, 9)
void mf_kernel(const int* __restrict__ dow,
               const int* __restrict__ tim,
               const int* __restrict__ mon,
               const int* __restrict__ day,
               const int* __restrict__ dest,
               const float* __restrict__ Wdow,
               const float* __restrict__ Wtim,
               const float* __restrict__ Wmon,
               const float* __restrict__ Wday,
               const float* __restrict__ Witem,
               float* __restrict__ out,
               int n)
{
    const int warp_id = blockIdx.x * WARPS_PER_BLOCK + (threadIdx.x >> 5);
    const int lane = threadIdx.x & 31;
    const int sub = lane >> 3;        // which small table (0..3)
    const int off = (lane & 7) * 4;   // float offset within 32-dim embedding

    const float* __restrict__ Wsub =
        (sub == 0) ? Wdow : (sub == 1) ? Wtim : (sub == 2) ? Wmon : Wday;
    const int* __restrict__ idx_arr =
        (sub == 0) ? dow : (sub == 1) ? tim : (sub == 2) ? mon : day;

    // Lane that ends up holding row i of the batch after the merged tree:
    //   bit4(lane)=i bit0, bit3(lane)=i bit1, bit2(lane)=i bit2, bits0-1=0.
    const int rowid = ((lane >> 4) & 1) | (((lane >> 3) & 1) << 1) | (((lane >> 2) & 1) << 2);
    const bool is_writer = ((lane & 3) == 0);

    const int base = warp_id * ROWS_PER_WARP;
    if (base >= n) return;

#pragma unroll
    for (int b = 0; b < ROWS_PER_WARP / BATCH; b++) {
        const int rb = base + b * BATCH;

        // ---- Vectorized index loads: rb is 8-aligned -> 32B-aligned int4 ----
        int si_v[BATCH];
        int di_v[BATCH];
        {
            const int4 ia = *reinterpret_cast<const int4*>(idx_arr + rb);
            const int4 ib = *reinterpret_cast<const int4*>(idx_arr + rb + 4);
            const int4 da = *reinterpret_cast<const int4*>(dest + rb);
            const int4 db = *reinterpret_cast<const int4*>(dest + rb + 4);
            si_v[0] = ia.x; si_v[1] = ia.y; si_v[2] = ia.z; si_v[3] = ia.w;
            si_v[4] = ib.x; si_v[5] = ib.y; si_v[6] = ib.z; si_v[7] = ib.w;
            di_v[0] = da.x; di_v[1] = da.y; di_v[2] = da.z; di_v[3] = da.w;
            di_v[4] = db.x; di_v[5] = db.y; di_v[6] = db.z; di_v[7] = db.w;
        }

        // ---- All 16 data loads front-batched (max MLP on the L2 path) ----
        float s[BATCH];
#pragma unroll
        for (int i = 0; i < BATCH; i++) {
            const float4 u = *reinterpret_cast<const float4*>(Wsub + (si_v[i] * 32 + off));
            const float4 v = *reinterpret_cast<const float4*>(Witem + (di_v[i] * 128 + lane * 4));
            float acc = u.x * v.x;
            acc = fmaf(u.y, v.y, acc);
            acc = fmaf(u.z, v.z, acc);
            acc = fmaf(u.w, v.w, acc);
            s[i] = acc;
        }

        // ---- Merged reduction: 16 shuffles for 8 rows ----
#pragma unroll
        for (int i = 0; i < BATCH; i++)
            s[i] += __shfl_xor_sync(0xFFFFFFFFu, s[i], 16);
        float t[4];
#pragma unroll
        for (int i = 0; i < 4; i++)
            t[i] = (lane < 16) ? s[2 * i] : s[2 * i + 1];
#pragma unroll
        for (int i = 0; i < 4; i++)
            t[i] += __shfl_xor_sync(0xFFFFFFFFu, t[i], 8);
        float q[2];
#pragma unroll
        for (int i = 0; i < 2; i++)
            q[i] = ((lane & 8) == 0) ? t[2 * i] : t[2 * i + 1];
#pragma unroll
        for (int i = 0; i < 2; i++)
            q[i] += __shfl_xor_sync(0xFFFFFFFFu, q[i], 4);
        float z = ((lane & 4) == 0) ? q[0] : q[1];
        z += __shfl_xor_sync(0xFFFFFFFFu, z, 2);
        z += __shfl_xor_sync(0xFFFFFFFFu, z, 1);

        // 8 writer lanes, contiguous out[rb..rb+7] -> one 32B sector.
        if (is_writer) out[rb + rowid] = z;
    }
}

extern "C" void kernel_launch(void* const* d_in, const int* in_sizes, int n_in,
                              void* d_out, int out_size)
{
    const int*   dow   = (const int*)d_in[0];
    const int*   tim   = (const int*)d_in[1];
    const int*   mon   = (const int*)d_in[2];
    const int*   day   = (const int*)d_in[3];
    const int*   dest  = (const int*)d_in[4];
    const float* Wdow  = (const float*)d_in[5];
    const float* Wtim  = (const float*)d_in[6];
    const float* Wmon  = (const float*)d_in[7];
    const float* Wday  = (const float*)d_in[8];
    const float* Witem = (const float*)d_in[9];
    float* out = (float*)d_out;

    const int n = in_sizes[0];
    const int rows_per_block = WARPS_PER_BLOCK * ROWS_PER_WARP;  // 64
    const int grid = (n + rows_per_block - 1) / rows_per_block;

    mf_kernel<<<grid, THREADS>>>(dow, tim, mon, day, dest,
                                 Wdow, Wtim, Wmon, Wday, Witem, out, n);
}

// round 10
// speedup vs baseline: 1.4580x; 1.0232x over previous
#include <cuda_runtime.h>
#include <cuda_bf16.h>

// MatrixFactorization: out[r] = dot(concat(Wd[dow],Wt[time],Wm[month],Wdy[day]), W_item[dest])
// N=1048576, NUM_FACTOR=128, NUM_DIM=32.
//
// R10 = R9 body with the two 8-row batches manually software-pipelined:
//   idx0 -> data0 -> [idx1 issued here, overlapping data0 flight]
//        -> fma/reduce/store(0) -> data1 -> fma/reduce/store(1)
// Hides the ~250-580cyc index-load latency of batch 1 behind batch 0's
// data loads + epilogue. No min-blocks reg cap (spill-free demand ~60).

#define WARPS_PER_BLOCK 4
#define THREADS (WARPS_PER_BLOCK * 32)
#define BATCH 8
#define ROWS_PER_WARP 16   // 2 pipelined batches of 8

struct Idx8 { int si[BATCH]; int di[BATCH]; };

__device__ __forceinline__ void load_idx(const int* __restrict__ idx_arr,
                                         const int* __restrict__ dest,
                                         int rb, Idx8& o)
{
    const int4 ia = *reinterpret_cast<const int4*>(idx_arr + rb);
    const int4 ib = *reinterpret_cast<const int4*>(idx_arr + rb + 4);
    const int4 da = *reinterpret_cast<const int4*>(dest + rb);
    const int4 db = *reinterpret_cast<const int4*>(dest + rb + 4);
    o.si[0] = ia.x; o.si[1] = ia.y; o.si[2] = ia.z; o.si[3] = ia.w;
    o.si[4] = ib.x; o.si[5] = ib.y; o.si[6] = ib.z; o.si[7] = ib.w;
    o.di[0] = da.x; o.di[1] = da.y; o.di[2] = da.z; o.di[3] = da.w;
    o.di[4] = db.x; o.di[5] = db.y; o.di[6] = db.z; o.di[7] = db.w;
}

__device__ __forceinline__ void load_data(const float* __restrict__ Wsub,
                                          const float* __restrict__ Witem,
                                          const Idx8& ix, int off, int lane,
                                          float4* u, float4* v)
{
#pragma unroll
    for (int i = 0; i < BATCH; i++)
        v[i] = *reinterpret_cast<const float4*>(Witem + (ix.di[i] * 128 + lane * 4));
#pragma unroll
    for (int i = 0; i < BATCH; i++)
        u[i] = *reinterpret_cast<const float4*>(Wsub + (ix.si[i] * 32 + off));
}

__device__ __forceinline__ void reduce_store(const float4* u, const float4* v,
                                             float* __restrict__ out, int rb,
                                             int lane, int rowid, bool is_writer)
{
    float s[BATCH];
#pragma unroll
    for (int i = 0; i < BATCH; i++) {
        float acc = u[i].x * v[i].x;
        acc = fmaf(u[i].y, v[i].y, acc);
        acc = fmaf(u[i].z, v[i].z, acc);
        acc = fmaf(u[i].w, v[i].w, acc);
        s[i] = acc;
    }
#pragma unroll
    for (int i = 0; i < BATCH; i++)
        s[i] += __shfl_xor_sync(0xFFFFFFFFu, s[i], 16);
    float t[4];
#pragma unroll
    for (int i = 0; i < 4; i++)
        t[i] = (lane < 16) ? s[2 * i] : s[2 * i + 1];
#pragma unroll
    for (int i = 0; i < 4; i++)
        t[i] += __shfl_xor_sync(0xFFFFFFFFu, t[i], 8);
    float q[2];
#pragma unroll
    for (int i = 0; i < 2; i++)
        q[i] = ((lane & 8) == 0) ? t[2 * i] : t[2 * i + 1];
#pragma unroll
    for (int i = 0; i < 2; i++)
        q[i] += __shfl_xor_sync(0xFFFFFFFFu, q[i], 4);
    float z = ((lane & 4) == 0) ? q[0] : q[1];
    z += __shfl_xor_sync(0xFFFFFFFFu, z, 2);
    z += __shfl_xor_sync(0xFFFFFFFFu, z, 1);

    if (is_writer) out[rb + rowid] = z;
}

__global__ __launch_bounds__(THREADS)
void mf_kernel(const int* __restrict__ dow,
               const int* __restrict__ tim,
               const int* __restrict__ mon,
               const int* __restrict__ day,
               const int* __restrict__ dest,
               const float* __restrict__ Wdow,
               const float* __restrict__ Wtim,
               const float* __restrict__ Wmon,
               const float* __restrict__ Wday,
               const float* __restrict__ Witem,
               float* __restrict__ out,
               int n)
{
    const int warp_id = blockIdx.x * WARPS_PER_BLOCK + (threadIdx.x >> 5);
    const int lane = threadIdx.x & 31;
    const int sub = lane >> 3;
    const int off = (lane & 7) * 4;

    const float* __restrict__ Wsub =
        (sub == 0) ? Wdow : (sub == 1) ? Wtim : (sub == 2) ? Wmon : Wday;
    const int* __restrict__ idx_arr =
        (sub == 0) ? dow : (sub == 1) ? tim : (sub == 2) ? mon : day;

    const int rowid = ((lane >> 4) & 1) | (((lane >> 3) & 1) << 1) | (((lane >> 2) & 1) << 2);
    const bool is_writer = ((lane & 3) == 0);

    const int base = warp_id * ROWS_PER_WARP;
    if (base >= n) return;
    const int rb0 = base;
    const int rb1 = base + BATCH;

    // ---- Pipelined schedule ----
    Idx8 ix0, ix1;
    float4 u0[BATCH], v0[BATCH];
    float4 u1[BATCH], v1[BATCH];

    load_idx(idx_arr, dest, rb0, ix0);          // idx0
    load_data(Wsub, Witem, ix0, off, lane, u0, v0);  // data0 (16 loads in flight)
    load_idx(idx_arr, dest, rb1, ix1);          // idx1 overlaps data0 flight

    reduce_store(u0, v0, out, rb0, lane, rowid, is_writer);  // epilogue0

    load_data(Wsub, Witem, ix1, off, lane, u1, v1);  // data1: idx1 already resident
    reduce_store(u1, v1, out, rb1, lane, rowid, is_writer);  // epilogue1
}

extern "C" void kernel_launch(void* const* d_in, const int* in_sizes, int n_in,
                              void* d_out, int out_size)
{
    const int*   dow   = (const int*)d_in[0];
    const int*   tim   = (const int*)d_in[1];
    const int*   mon   = (const int*)d_in[2];
    const int*   day   = (const int*)d_in[3];
    const int*   dest  = (const int*)d_in[4];
    const float* Wdow  = (const float*)d_in[5];
    const float* Wtim  = (const float*)d_in[6];
    const float* Wmon  = (const float*)d_in[7];
    const float* Wday  = (const float*)d_in[8];
    const float* Witem = (const float*)d_in[9];
    float* out = (float*)d_out;

    const int n = in_sizes[0];
    const int rows_per_block = WARPS_PER_BLOCK * ROWS_PER_WARP;  // 64
    const int grid = (n + rows_per_block - 1) / rows_per_block;

    mf_kernel<<<grid, THREADS>>>(dow, tim, mon, day, dest,
                                 Wdow, Wtim, Wmon, Wday, Witem, out, n);
}